// round 9
// baseline (speedup 1.0000x reference)
#include <cuda_runtime.h>

// Problem constants (static per reference)
#define BSZ   128
#define NTOT  129
#define NPT   128          // N
#define GS    16
#define CH    384          // channels
#define CH4   96           // CH / 4 (float4 units per row)
#define EPSW  0.05f
#define RMSEPS 1e-6f

#define NPAIRS 8192        // (BSZ*NPT)/2
#define NBLK   1776        // 148 SMs * 12 CTAs  (persistent grid)

__global__ __launch_bounds__(96, 12)
void K_Rectify_38216619000515_kernel(
    const float* __restrict__ f,        // (B, NTOT, CH)
    const float* __restrict__ distance, // (B, N, GS)
    const float* __restrict__ rf,       // (NTOT, CH)
    const float* __restrict__ knorm_w,  // (CH,)
    const int*   __restrict__ idx,      // (B, N, GS), int32, values in [0, B*N)
    float*       __restrict__ out)      // (B, NTOT, CH)
{
    const int tid  = threadIdx.x;        // 0..95
    const int w    = tid >> 5;
    const int lane = tid & 31;

    __shared__ float4 sgw[2][GS];        // (offA bits, wtA, offB bits, wtB), offsets in float4 units
    __shared__ float  red[2][2][3];      // [parity][point][warp]

    const int p = tid >> 4;              // 0/1 (for tid<32): which point of the pair
    const int g = tid & 15;

    // preload table for first pair
    if (tid < 2 * GS) {
        const int bn = (blockIdx.x << 1) + p;
        float d  = distance[bn * GS + g];
        float wt = 1.0f / (d + EPSW);
        int r    = idx[bn * GS + g] & (BSZ * NPT - 1);
        int off  = ((r >> 7) * NTOT + (r & 127) + 1) * CH4;   // float4 units
        if (p == 0) { sgw[0][g].x = __int_as_float(off); sgw[0][g].y = wt; }
        else        { sgw[0][g].z = __int_as_float(off); sgw[0][g].w = wt; }
    }
    __syncthreads();

    const float4* f4  = (const float4*)f;
    const float4 kv   = __ldg((const float4*)knorm_w + tid);   // loop-invariant

    int parity = 0;
    for (int pb = blockIdx.x; pb < NPAIRS; pb += NBLK) {
        const int bn0 = pb << 1;
        const int bn1 = bn0 | 1;
        const int b0 = bn0 >> 7, n0 = bn0 & 127;
        const int n1 = n0 | 1;                   // same b, odd n -> never cls

        // ---- prefetch next pair's table inputs (latency hidden under gathers) ----
        float nd = 0.0f; int nr = 0;
        const bool hasNext = (pb + NBLK < NPAIRS) && (tid < 2 * GS);
        if (hasNext) {
            const int bn = ((pb + NBLK) << 1) + p;
            nd = distance[bn * GS + g];
            nr = idx[bn * GS + g];
        }

        // cls token passthrough (only point A can have n==0); 96 lanes == CH4
        if (n0 == 0) {
            ((float4*)out)[b0 * (NTOT * CH4) + tid] =
                __ldg(f4 + b0 * (NTOT * CH4) + tid);
        }

        float wsA = 0.0f, wsB = 0.0f;
#pragma unroll
        for (int k = 0; k < GS; ++k) { wsA += sgw[parity][k].y; wsB += sgw[parity][k].w; }
        const float iwA = 1.0f / wsA;
        const float iwB = 1.0f / wsB;

        const int xrowA = (b0 * NTOT + 1 + n0) * CH4;
        const int xrowB = (b0 * NTOT + 1 + n1) * CH4;

        float4 sa = make_float4(0.f,0.f,0.f,0.f);
        float4 sb = make_float4(0.f,0.f,0.f,0.f);
#pragma unroll
        for (int k = 0; k < GS; ++k) {
            const float4 q = sgw[parity][k];         // one LDS.128 broadcast per k
            const float4 va = __ldg(f4 + __float_as_int(q.x) + tid);
            const float4 vb = __ldg(f4 + __float_as_int(q.z) + tid);
            const float wa = q.y, wb = q.w;
            sa.x = fmaf(wa, va.x, sa.x); sa.y = fmaf(wa, va.y, sa.y);
            sa.z = fmaf(wa, va.z, sa.z); sa.w = fmaf(wa, va.w, sa.w);
            sb.x = fmaf(wb, vb.x, sb.x); sb.y = fmaf(wb, vb.y, sb.y);
            sb.z = fmaf(wb, vb.z, sb.z); sb.w = fmaf(wb, vb.w, sb.w);
        }
        const float4 xa = __ldg(f4 + xrowA + tid);
        const float4 xb = __ldg(f4 + xrowB + tid);

        // ---- publish next pair's table (other parity; readers separated by the sync below) ----
        if (hasNext) {
            float wt = 1.0f / (nd + EPSW);
            int r    = nr & (BSZ * NPT - 1);
            int off  = ((r >> 7) * NTOT + (r & 127) + 1) * CH4;
            if (p == 0) { sgw[parity ^ 1][g].x = __int_as_float(off); sgw[parity ^ 1][g].y = wt; }
            else        { sgw[parity ^ 1][g].z = __int_as_float(off); sgw[parity ^ 1][g].w = wt; }
        }

        // (sum w*row)/W - x   (weights normalized in reference)
        sa.x = sa.x*iwA - xa.x; sa.y = sa.y*iwA - xa.y;
        sa.z = sa.z*iwA - xa.z; sa.w = sa.w*iwA - xa.w;
        sb.x = sb.x*iwB - xb.x; sb.y = sb.y*iwB - xb.y;
        sb.z = sb.z*iwB - xb.z; sb.w = sb.w*iwB - xb.w;

        float lA = sa.x*sa.x + sa.y*sa.y + sa.z*sa.z + sa.w*sa.w;
        float lB = sb.x*sb.x + sb.y*sb.y + sb.z*sb.z + sb.w*sb.w;
#pragma unroll
        for (int off = 16; off > 0; off >>= 1) {
            lA += __shfl_down_sync(0xffffffffu, lA, off);
            lB += __shfl_down_sync(0xffffffffu, lB, off);
        }
        if (lane == 0) { red[parity][0][w] = lA; red[parity][1][w] = lB; }
        __syncthreads();   // single barrier per iteration

        const float riA = rsqrtf((red[parity][0][0] + red[parity][0][1] + red[parity][0][2])
                                 * (1.0f / CH) + RMSEPS);
        const float riB = rsqrtf((red[parity][1][0] + red[parity][1][1] + red[parity][1][2])
                                 * (1.0f / CH) + RMSEPS);

        const float4 rvA = __ldg((const float4*)rf + (1 + n0) * CH4 + tid);
        const float4 rvB = __ldg((const float4*)rf + (1 + n1) * CH4 + tid);

        float4 o;
        o.x = rvA.x + xa.x + sa.x*riA*kv.x;  o.y = rvA.y + xa.y + sa.y*riA*kv.y;
        o.z = rvA.z + xa.z + sa.z*riA*kv.z;  o.w = rvA.w + xa.w + sa.w*riA*kv.w;
        ((float4*)out)[xrowA + tid] = o;
        o.x = rvB.x + xb.x + sb.x*riB*kv.x;  o.y = rvB.y + xb.y + sb.y*riB*kv.y;
        o.z = rvB.z + xb.z + sb.z*riB*kv.z;  o.w = rvB.w + xb.w + sb.w*riB*kv.w;
        ((float4*)out)[xrowB + tid] = o;

        parity ^= 1;
    }
}

extern "C" void kernel_launch(void* const* d_in, const int* in_sizes, int n_in,
                              void* d_out, int out_size)
{
    const float* f        = (const float*)d_in[0];
    const float* distance = (const float*)d_in[1];
    const float* rf       = (const float*)d_in[2];
    const float* knorm_w  = (const float*)d_in[3];
    const int*   idx      = (const int*)d_in[4];
    float*       out      = (float*)d_out;

    K_Rectify_38216619000515_kernel<<<NBLK, 96>>>(
        f, distance, rf, knorm_w, idx, out);
}